// round 3
// baseline (speedup 1.0000x reference)
#include <cuda_runtime.h>
#include <cuda_bf16.h>
#include <math.h>

#define Bq 64
#define Nq 4096
#define Dq 256
#define Sq 8
#define Hq 512
#define ROWS (Bq*Sq)          // 512 slot rows total
#define SCALEF 0.0625f        // 256^-0.5
#define LN_EPS 1e-5f
#define EPS_A 1e-8f

#define ATILE 32              // tokens per tile in attend kernel
#define ATPB 16               // tiles per block -> 512 tokens per block
#define CHUNKS (Nq/(ATILE*ATPB))   // 8 chunks per batch

// -------------------- scratch (device globals; no allocation) --------------------
__device__ float g_xln[(size_t)Bq*Nq*Dq];      // 256 MB: LN(inputs)
__device__ float g_slots[ROWS*Dq];
__device__ float g_s[ROWS*Dq];
__device__ float g_q[ROWS*Dq];
__device__ float g_qk[ROWS*Dq];
__device__ float g_c[ROWS];
__device__ float g_numer[ROWS*Dq];             // normalized numer (A for upd GEMM)
__device__ float g_part[(size_t)CHUNKS*ROWS*Dq];
__device__ float g_dpart[CHUNKS*ROWS];
__device__ float g_upd[ROWS*Dq];
__device__ float g_gx[ROWS*3*Dq];
__device__ float g_gh[ROWS*3*Dq];
__device__ float g_h[ROWS*Dq];
__device__ float g_hln[ROWS*Dq];
__device__ float g_ff1[ROWS*Hq];

// -------------------- LayerNorm over rows of width 256 --------------------
__global__ void ln_rows_kernel(const float* __restrict__ x, const float* __restrict__ w,
                               const float* __restrict__ bb, float* __restrict__ y) {
    __shared__ float sm[8];
    __shared__ float sm2[8];
    size_t row = blockIdx.x;
    int t = threadIdx.x;
    float v = x[row*Dq + t];
    float s = v;
    #pragma unroll
    for (int o = 16; o > 0; o >>= 1) s += __shfl_xor_sync(0xffffffffu, s, o);
    if ((t & 31) == 0) sm[t >> 5] = s;
    __syncthreads();
    float mean = 0.f;
    #pragma unroll
    for (int i = 0; i < 8; i++) mean += sm[i];
    mean *= (1.0f/Dq);
    float d = v - mean;
    float sq = d*d;
    #pragma unroll
    for (int o = 16; o > 0; o >>= 1) sq += __shfl_xor_sync(0xffffffffu, sq, o);
    if ((t & 31) == 0) sm2[t >> 5] = sq;
    __syncthreads();
    float var = 0.f;
    #pragma unroll
    for (int i = 0; i < 8; i++) var += sm2[i];
    var *= (1.0f/Dq);
    y[row*Dq + t] = d * rsqrtf(var + LN_EPS) * w[t] + bb[t];
}

// -------------------- init slots from query_pos --------------------
__global__ void init_slots_kernel(const float* __restrict__ qp, float* __restrict__ slots) {
    int row = blockIdx.x, d = threadIdx.x;
    slots[row*Dq + d] = qp[(row & 7)*Dq + d];
}

// -------------------- c[row] = SCALE * dot(q_row, bk) --------------------
__global__ void cvec_kernel(const float* __restrict__ q, const float* __restrict__ bk,
                            float* __restrict__ c) {
    __shared__ float sm[8];
    int row = blockIdx.x, t = threadIdx.x;
    float p = q[row*Dq + t] * bk[t];
    #pragma unroll
    for (int o = 16; o > 0; o >>= 1) p += __shfl_xor_sync(0xffffffffu, p, o);
    if ((t & 31) == 0) sm[t >> 5] = p;
    __syncthreads();
    if (t == 0) {
        float s = 0.f;
        #pragma unroll
        for (int i = 0; i < 8; i++) s += sm[i];
        c[row] = SCALEF * s;
    }
}

// -------------------- small generic SGEMM: C = act(alpha*A@op(W) + bias) + res ----
// TRANSW: W stored [N,K] (PyTorch Linear), else W stored [K,N].
template<bool TRANSW, bool RELU>
__global__ void gemm_kernel(const float* __restrict__ A, const float* __restrict__ W,
                            const float* __restrict__ bias, const float* __restrict__ res,
                            float* __restrict__ C, int M, int N, int K, float alpha) {
    const int BK = 16;
    __shared__ float As[BK][65];
    __shared__ float Bs[BK][65];
    int m0 = blockIdx.y * 64, n0 = blockIdx.x * 64;
    int tid = threadIdx.x;
    int tx = tid & 15, ty = tid >> 4;
    float acc[4][4] = {};
    for (int k0 = 0; k0 < K; k0 += BK) {
        #pragma unroll
        for (int i = 0; i < 4; i++) {
            int idx = tid + i*256;
            int m = idx >> 4, k = idx & 15;
            As[k][m] = A[(size_t)(m0 + m)*K + k0 + k];
        }
        #pragma unroll
        for (int i = 0; i < 4; i++) {
            int idx = tid + i*256;
            if (TRANSW) {
                int n = idx >> 4, k = idx & 15;
                Bs[k][n] = W[(size_t)(n0 + n)*K + k0 + k];
            } else {
                int k = idx >> 6, n = idx & 63;
                Bs[k][n] = W[(size_t)(k0 + k)*N + n0 + n];
            }
        }
        __syncthreads();
        #pragma unroll
        for (int k = 0; k < BK; k++) {
            float a[4], b[4];
            #pragma unroll
            for (int j = 0; j < 4; j++) a[j] = As[k][ty*4 + j];
            #pragma unroll
            for (int j = 0; j < 4; j++) b[j] = Bs[k][tx*4 + j];
            #pragma unroll
            for (int i = 0; i < 4; i++)
                #pragma unroll
                for (int j = 0; j < 4; j++)
                    acc[i][j] = fmaf(a[i], b[j], acc[i][j]);
        }
        __syncthreads();
    }
    #pragma unroll
    for (int i = 0; i < 4; i++) {
        int m = m0 + ty*4 + i;
        #pragma unroll
        for (int j = 0; j < 4; j++) {
            int n = n0 + tx*4 + j;
            float v = acc[i][j]*alpha;
            if (bias) v += bias[n];
            if (RELU) v = fmaxf(v, 0.f);
            if (res)  v += res[(size_t)m*N + n];
            C[(size_t)m*N + n] = v;
        }
    }
}

// -------------------- fused attend: per-token softmax over slots, stream xln ------
// logits_i(token) = qk[b,i,:] . x + c[b,i]   (qk pre-scaled by SCALE)
// a_i = softmax_i + EPS ; numer_i += a_i*x ; denom_i += a_i  (partials per chunk)
__global__ void attend_kernel(const float* __restrict__ xln,
                              const float* __restrict__ qk,
                              const float* __restrict__ cc,
                              float* __restrict__ part,
                              float* __restrict__ dpart) {
    __shared__ float x_s[ATILE*257];
    __shared__ float qk_s[8*256];
    __shared__ float a_s[ATILE*8];
    __shared__ float c_s[8];
    int b = blockIdx.y;
    int t = threadIdx.x;
    #pragma unroll
    for (int i = 0; i < 8; i++) qk_s[i*256 + t] = qk[(b*8 + i)*256 + t];
    if (t < 8) c_s[t] = cc[b*8 + t];
    float acc[8] = {0,0,0,0,0,0,0,0};
    float dsum = 0.f;
    size_t tok0 = (size_t)blockIdx.x * (ATILE*ATPB);
    const float* xb = xln + ((size_t)b*Nq + tok0)*Dq;
    int tokA = t & 31;
    int slotA = t >> 5;
    const float* qrow = qk_s + slotA*256;
    const float* xrowA = x_s + tokA*257;
    for (int tile = 0; tile < ATPB; tile++) {
        const float* xt = xb + (size_t)tile*ATILE*Dq;
        __syncthreads();  // protect x_s/a_s reuse across tiles (also covers qk_s init)
        // stage 32x256 floats via float4 global loads, scalar smem stores (pad 257)
        #pragma unroll
        for (int i = 0; i < 8; i++) {
            int f4 = i*256 + t;
            int row = f4 >> 6, c4 = (f4 & 63) << 2;
            float4 v = *(const float4*)(xt + row*256 + c4);
            float* dst = x_s + row*257 + c4;
            dst[0] = v.x; dst[1] = v.y; dst[2] = v.z; dst[3] = v.w;
        }
        __syncthreads();
        // phase A: one logit per thread (token tokA, slot slotA)
        float l = c_s[slotA];
        #pragma unroll 8
        for (int d = 0; d < 256; d++) l = fmaf(xrowA[d], qrow[d], l);
        a_s[tokA*8 + slotA] = l;
        __syncthreads();
        // softmax over 8 slots, one token per thread (threads 0..31)
        if (t < 32) {
            float lv[8], m = -1e30f;
            #pragma unroll
            for (int i = 0; i < 8; i++) { lv[i] = a_s[t*8 + i]; m = fmaxf(m, lv[i]); }
            float ssum = 0.f;
            #pragma unroll
            for (int i = 0; i < 8; i++) { lv[i] = __expf(lv[i] - m); ssum += lv[i]; }
            float inv = 1.0f/ssum;
            #pragma unroll
            for (int i = 0; i < 8; i++) a_s[t*8 + i] = lv[i]*inv + EPS_A;
        }
        __syncthreads();
        // denom partials (threads 0..7, slot = t)
        if (t < 8) {
            #pragma unroll
            for (int j = 0; j < ATILE; j++) dsum += a_s[j*8 + t];
        }
        // phase B: thread owns d = t, rank-1 accumulate over tokens
        #pragma unroll 4
        for (int j = 0; j < ATILE; j++) {
            float xv = x_s[j*257 + t];
            float4 a0 = *(const float4*)(a_s + j*8);
            float4 a1 = *(const float4*)(a_s + j*8 + 4);
            acc[0] = fmaf(a0.x, xv, acc[0]);
            acc[1] = fmaf(a0.y, xv, acc[1]);
            acc[2] = fmaf(a0.z, xv, acc[2]);
            acc[3] = fmaf(a0.w, xv, acc[3]);
            acc[4] = fmaf(a1.x, xv, acc[4]);
            acc[5] = fmaf(a1.y, xv, acc[5]);
            acc[6] = fmaf(a1.z, xv, acc[6]);
            acc[7] = fmaf(a1.w, xv, acc[7]);
        }
    }
    // deterministic partial writes (reduced by reduce_norm_kernel)
    #pragma unroll
    for (int i = 0; i < 8; i++)
        part[((size_t)blockIdx.x*ROWS + b*8 + i)*Dq + t] = acc[i];
    if (t < 8)
        dpart[blockIdx.x*ROWS + b*8 + t] = dsum;
}

// -------------------- reduce partials over chunks and normalize --------------------
__global__ void reduce_norm_kernel(const float* __restrict__ part,
                                   const float* __restrict__ dpart,
                                   float* __restrict__ numer) {
    int row = blockIdx.x, t = threadIdx.x;
    float s = 0.f, dn = 0.f;
    #pragma unroll
    for (int c = 0; c < CHUNKS; c++) {
        s  += part[((size_t)c*ROWS + row)*Dq + t];
        dn += dpart[c*ROWS + row];
    }
    numer[(size_t)row*Dq + t] = s / dn;
}

// -------------------- GRU cell elementwise --------------------
__global__ void gru_kernel(const float* __restrict__ gx, const float* __restrict__ gh,
                           const float* __restrict__ slots, float* __restrict__ h) {
    int row = blockIdx.x, d = threadIdx.x;
    const float* gxr = gx + (size_t)row*768;
    const float* ghr = gh + (size_t)row*768;
    float r = 1.f/(1.f + expf(-(gxr[d]       + ghr[d])));
    float z = 1.f/(1.f + expf(-(gxr[256 + d] + ghr[256 + d])));
    float n = tanhf(gxr[512 + d] + r*ghr[512 + d]);
    h[(size_t)row*Dq + d] = (1.f - z)*n + z*slots[(size_t)row*Dq + d];
}

// -------------------- host --------------------
extern "C" void kernel_launch(void* const* d_in, const int* in_sizes, int n_in,
                              void* d_out, int out_size) {
    (void)in_sizes; (void)n_in; (void)out_size;
    const float* inputs    = (const float*)d_in[0];
    const float* query_pos = (const float*)d_in[1];
    const float* wq   = (const float*)d_in[2];
    const float* bq   = (const float*)d_in[3];
    const float* wk   = (const float*)d_in[4];
    const float* bk   = (const float*)d_in[5];
    const float* wv   = (const float*)d_in[6];
    const float* bv   = (const float*)d_in[7];
    const float* w_ih = (const float*)d_in[8];
    const float* b_ih = (const float*)d_in[9];
    const float* w_hh = (const float*)d_in[10];
    const float* b_hh = (const float*)d_in[11];
    const float* w1   = (const float*)d_in[12];
    const float* b1   = (const float*)d_in[13];
    const float* w2   = (const float*)d_in[14];
    const float* b2   = (const float*)d_in[15];
    const float* ln_in_w = (const float*)d_in[16];
    const float* ln_in_b = (const float*)d_in[17];
    const float* ln_s_w  = (const float*)d_in[18];
    const float* ln_s_b  = (const float*)d_in[19];
    const float* ln_ff_w = (const float*)d_in[20];
    const float* ln_ff_b = (const float*)d_in[21];
    float* out = (float*)d_out;

    float *xln, *slots, *s, *q, *qk, *c, *numer, *part, *dpart, *upd, *gx, *gh, *h, *hln, *ff1;
    cudaGetSymbolAddress((void**)&xln,   g_xln);
    cudaGetSymbolAddress((void**)&slots, g_slots);
    cudaGetSymbolAddress((void**)&s,     g_s);
    cudaGetSymbolAddress((void**)&q,     g_q);
    cudaGetSymbolAddress((void**)&qk,    g_qk);
    cudaGetSymbolAddress((void**)&c,     g_c);
    cudaGetSymbolAddress((void**)&numer, g_numer);
    cudaGetSymbolAddress((void**)&part,  g_part);
    cudaGetSymbolAddress((void**)&dpart, g_dpart);
    cudaGetSymbolAddress((void**)&upd,   g_upd);
    cudaGetSymbolAddress((void**)&gx,    g_gx);
    cudaGetSymbolAddress((void**)&gh,    g_gh);
    cudaGetSymbolAddress((void**)&h,     g_h);
    cudaGetSymbolAddress((void**)&hln,   g_hln);
    cudaGetSymbolAddress((void**)&ff1,   g_ff1);

    // xln = LN(inputs)  (computed once, reused by all 4 steps)
    ln_rows_kernel<<<Bq*Nq, 256>>>(inputs, ln_in_w, ln_in_b, xln);
    init_slots_kernel<<<ROWS, 256>>>(query_pos, slots);

    for (int it = 0; it < 4; it++) {
        float* slots_out = (it == 3) ? out : slots;
        // s = LN(slots); q = s@wq.T + bq; qk = SCALE*(q@wk); c = SCALE*(q.bk)
        ln_rows_kernel<<<ROWS, 256>>>(slots, ln_s_w, ln_s_b, s);
        gemm_kernel<true,  false><<<dim3(4, 8), 256>>>(s, wq, bq, nullptr, q, ROWS, Dq, Dq, 1.f);
        gemm_kernel<false, false><<<dim3(4, 8), 256>>>(q, wk, nullptr, nullptr, qk, ROWS, Dq, Dq, SCALEF);
        cvec_kernel<<<ROWS, 256>>>(q, bk, c);
        // fused streaming attention over xln
        attend_kernel<<<dim3(CHUNKS, Bq), 256>>>(xln, qk, c, part, dpart);
        reduce_norm_kernel<<<ROWS, 256>>>(part, dpart, numer);
        // updates = (numer/denom)@wv.T + bv
        gemm_kernel<true, false><<<dim3(4, 8), 256>>>(numer, wv, bv, nullptr, upd, ROWS, Dq, Dq, 1.f);
        // GRU gates
        gemm_kernel<true, false><<<dim3(12, 8), 256>>>(upd,   w_ih, b_ih, nullptr, gx, ROWS, 3*Dq, Dq, 1.f);
        gemm_kernel<true, false><<<dim3(12, 8), 256>>>(slots, w_hh, b_hh, nullptr, gh, ROWS, 3*Dq, Dq, 1.f);
        gru_kernel<<<ROWS, 256>>>(gx, gh, slots, h);
        // FF: slots_out = h + relu(LN(h)@w1.T + b1)@w2.T + b2
        ln_rows_kernel<<<ROWS, 256>>>(h, ln_ff_w, ln_ff_b, hln);
        gemm_kernel<true, true ><<<dim3(8, 8), 256>>>(hln, w1, b1, nullptr, ff1, ROWS, Hq, Dq, 1.f);
        gemm_kernel<true, false><<<dim3(4, 8), 256>>>(ff1, w2, b2, h, slots_out, ROWS, Dq, Hq, 1.f);
    }
}

// round 4
// speedup vs baseline: 1.2474x; 1.2474x over previous
#include <cuda_runtime.h>
#include <cuda_bf16.h>
#include <math.h>

#define Bq 64
#define Nq 4096
#define Dq 256
#define Hq 512
#define ROWS 512              // Bq*8 slot rows
#define SCALEF 0.0625f        // 256^-0.5
#define LN_EPS 1e-5f
#define EPS_A 1e-8f

#define TPW 4                 // tokens per warp (attend)
#define TILE_TOK 32           // tokens per block-tile (8 warps * 4)
#define ATPB2 8               // tiles per block -> 256 tokens/block
#define ACH (Nq/(TILE_TOK*ATPB2))   // 16 chunks per batch

// -------------------- scratch (device globals; no allocation) --------------------
__device__ float g_xln[(size_t)Bq*Nq*Dq];      // 256 MB: LN(inputs)
__device__ float g_slots[ROWS*Dq];
__device__ float g_s[ROWS*Dq];
__device__ float g_qk[ROWS*Dq];
__device__ float g_c[ROWS];
__device__ float g_numer[ROWS*Dq];
__device__ float g_part[(size_t)ACH*ROWS*Dq];
__device__ float g_dpart[ACH*ROWS];
__device__ float g_upd[ROWS*Dq];
__device__ float g_gx[ROWS*3*Dq];
__device__ float g_gh[ROWS*3*Dq];
__device__ float g_h[ROWS*Dq];
__device__ float g_hln[ROWS*Dq];
__device__ float g_ff1[ROWS*Hq];
__device__ float g_w2t[Dq*Dq];     // w2t[n][k] = SCALE * sum_e wq[e][k]*wk[e][n]
__device__ float g_vb[Dq];         // vb[k] = SCALE * sum_e wq[e][k]*bk[e]
__device__ float g_bqk[Dq];        // bqk[n] = SCALE * sum_e bq[e]*wk[e][n]
__device__ float g_cconst[1];      // SCALE * (bq . bk)

// -------------------- LayerNorm over rows of width 256 --------------------
__global__ void ln_rows_kernel(const float* __restrict__ x, const float* __restrict__ w,
                               const float* __restrict__ bb, float* __restrict__ y) {
    __shared__ float sm[8];
    __shared__ float sm2[8];
    size_t row = blockIdx.x;
    int t = threadIdx.x;
    float v = x[row*Dq + t];
    float s = v;
    #pragma unroll
    for (int o = 16; o > 0; o >>= 1) s += __shfl_xor_sync(0xffffffffu, s, o);
    if ((t & 31) == 0) sm[t >> 5] = s;
    __syncthreads();
    float mean = 0.f;
    #pragma unroll
    for (int i = 0; i < 8; i++) mean += sm[i];
    mean *= (1.0f/Dq);
    float d = v - mean;
    float sq = d*d;
    #pragma unroll
    for (int o = 16; o > 0; o >>= 1) sq += __shfl_xor_sync(0xffffffffu, sq, o);
    if ((t & 31) == 0) sm2[t >> 5] = sq;
    __syncthreads();
    float var = 0.f;
    #pragma unroll
    for (int i = 0; i < 8; i++) var += sm2[i];
    var *= (1.0f/Dq);
    y[row*Dq + t] = d * rsqrtf(var + LN_EPS) * w[t] + bb[t];
}

// -------------------- init slots from query_pos --------------------
__global__ void init_slots_kernel(const float* __restrict__ qp, float* __restrict__ slots) {
    int row = blockIdx.x, d = threadIdx.x;
    slots[row*Dq + d] = qp[(row & 7)*Dq + d];
}

// -------------------- precompute W2T = SCALE * (wq.T @ wk) stored [n][k] ----------
__global__ void __launch_bounds__(256) prep_w2_kernel(const float* __restrict__ wq,
                                                      const float* __restrict__ wk,
                                                      float* __restrict__ w2t) {
    __shared__ float As[64][68];  // wq tile: [e][m(k-col)]
    __shared__ float Bs[64][68];  // wk tile: [e][n]
    int n0 = blockIdx.y * 64, m0 = blockIdx.x * 64;
    int t = threadIdx.x, tx = t & 15, ty = t >> 4;
    float acc[4][4] = {};
    for (int e0 = 0; e0 < Dq; e0 += 64) {
        #pragma unroll
        for (int i = 0; i < 4; i++) {
            int f4 = t + i*256;
            int r = f4 >> 4, cq = f4 & 15;
            float4 va = *(const float4*)(wq + (size_t)(e0 + r)*Dq + m0 + 4*cq);
            *(float4*)&As[r][4*cq] = va;
            float4 vb4 = *(const float4*)(wk + (size_t)(e0 + r)*Dq + n0 + 4*cq);
            *(float4*)&Bs[r][4*cq] = vb4;
        }
        __syncthreads();
        #pragma unroll
        for (int kk = 0; kk < 64; kk++) {
            float nv[4], mv[4];
            #pragma unroll
            for (int i = 0; i < 4; i++) nv[i] = Bs[kk][4*ty + i];
            #pragma unroll
            for (int j = 0; j < 4; j++) mv[j] = As[kk][4*tx + j];
            #pragma unroll
            for (int i = 0; i < 4; i++)
                #pragma unroll
                for (int j = 0; j < 4; j++)
                    acc[i][j] = fmaf(nv[i], mv[j], acc[i][j]);
        }
        __syncthreads();
    }
    #pragma unroll
    for (int i = 0; i < 4; i++)
        #pragma unroll
        for (int j = 0; j < 4; j++)
            w2t[(size_t)(n0 + 4*ty + i)*Dq + m0 + 4*tx + j] = SCALEF * acc[i][j];
}

// -------------------- precompute vb, bqk, cconst --------------------
__global__ void prep_small_kernel(const float* __restrict__ wq, const float* __restrict__ wk,
                                  const float* __restrict__ bq, const float* __restrict__ bk,
                                  float* __restrict__ vb, float* __restrict__ bqk,
                                  float* __restrict__ cconst) {
    int t = threadIdx.x;
    float a = 0.f, b = 0.f;
    for (int e = 0; e < Dq; e++) {
        a = fmaf(wq[e*Dq + t], bk[e], a);
        b = fmaf(bq[e], wk[e*Dq + t], b);
    }
    vb[t] = SCALEF * a;
    bqk[t] = SCALEF * b;
    if (t == 0) {
        float cst = 0.f;
        for (int e = 0; e < Dq; e++) cst += bq[e]*bk[e];
        cconst[0] = SCALEF * cst;
    }
}

// -------------------- c[row] = s_row . vb + cconst --------------------
__global__ void cvec2_kernel(const float* __restrict__ s, const float* __restrict__ vb,
                             const float* __restrict__ cconst, float* __restrict__ c) {
    __shared__ float sm[8];
    int row = blockIdx.x, t = threadIdx.x;
    float p = s[row*Dq + t] * vb[t];
    #pragma unroll
    for (int o = 16; o > 0; o >>= 1) p += __shfl_xor_sync(0xffffffffu, p, o);
    if ((t & 31) == 0) sm[t >> 5] = p;
    __syncthreads();
    if (t == 0) {
        float sum = 0.f;
        #pragma unroll
        for (int i = 0; i < 8; i++) sum += sm[i];
        c[row] = sum + cconst[0];
    }
}

// -------------------- GEMM 64x64 tile, BK=64: C = A@W^T + bias (+res) (relu) ------
// A:[M,K] row-major. W:[N,K] row-major (PyTorch Linear layout).
template<bool RELU>
__global__ void __launch_bounds__(256) gemm64_kernel(const float* __restrict__ A,
                                                     const float* __restrict__ W,
                                                     const float* __restrict__ bias,
                                                     const float* __restrict__ res,
                                                     float* __restrict__ C,
                                                     int M, int N, int K) {
    __shared__ float As[64][65];   // [m][k]
    __shared__ float Bs[64][65];   // [n][k]
    int m0 = blockIdx.y * 64, n0 = blockIdx.x * 64;
    int t = threadIdx.x, tx = t & 15, ty = t >> 4;
    float acc[4][4] = {};
    for (int k0 = 0; k0 < K; k0 += 64) {
        #pragma unroll
        for (int i = 0; i < 4; i++) {
            int f4 = t + i*256;
            int r = f4 >> 4, kq = f4 & 15;
            float4 va = *(const float4*)(A + (size_t)(m0 + r)*K + k0 + 4*kq);
            As[r][4*kq + 0] = va.x; As[r][4*kq + 1] = va.y;
            As[r][4*kq + 2] = va.z; As[r][4*kq + 3] = va.w;
            float4 vb4 = *(const float4*)(W + (size_t)(n0 + r)*K + k0 + 4*kq);
            Bs[r][4*kq + 0] = vb4.x; Bs[r][4*kq + 1] = vb4.y;
            Bs[r][4*kq + 2] = vb4.z; Bs[r][4*kq + 3] = vb4.w;
        }
        __syncthreads();
        #pragma unroll
        for (int kk = 0; kk < 64; kk++) {
            float a[4], b[4];
            #pragma unroll
            for (int i = 0; i < 4; i++) a[i] = As[4*ty + i][kk];
            #pragma unroll
            for (int j = 0; j < 4; j++) b[j] = Bs[4*tx + j][kk];
            #pragma unroll
            for (int i = 0; i < 4; i++)
                #pragma unroll
                for (int j = 0; j < 4; j++)
                    acc[i][j] = fmaf(a[i], b[j], acc[i][j]);
        }
        __syncthreads();
    }
    #pragma unroll
    for (int i = 0; i < 4; i++) {
        int m = m0 + 4*ty + i;
        #pragma unroll
        for (int j = 0; j < 4; j++) {
            int n = n0 + 4*tx + j;
            float v = acc[i][j];
            if (bias) v += bias[n];
            if (RELU) v = fmaxf(v, 0.f);
            if (res)  v += res[(size_t)m*N + n];
            C[(size_t)m*N + n] = v;
        }
    }
}

// -------------------- attend v2: x in registers, shfl-reduced logits --------------
// Per warp: 4 tokens; lane l owns d in {4l..4l+3} U {128+4l..128+4l+3}.
// logits replicated to all lanes via 5-round butterfly; softmax in-register.
__global__ void __launch_bounds__(256, 1) attend2_kernel(const float* __restrict__ xln,
                                                         const float* __restrict__ qk,
                                                         const float* __restrict__ cc,
                                                         float* __restrict__ part,
                                                         float* __restrict__ dpart) {
    __shared__ float4 qk4[512];   // [s][64] float4 view of qk[b] (8x256)
    __shared__ float red[2048];   // [s][256] block partial numer
    __shared__ float sds[64];     // [warp][slot] partial denom
    int b = blockIdx.y;
    int t = threadIdx.x, w = t >> 5, l = t & 31;
    {
        const float4* src = (const float4*)(qk + (size_t)b*8*Dq);
        qk4[t]       = src[t];
        qk4[t + 256] = src[t + 256];
    }
    float cr[8];
    #pragma unroll
    for (int s = 0; s < 8; s++) cr[s] = cc[b*8 + s];
    #pragma unroll
    for (int i = 0; i < 8; i++) red[t + i*256] = 0.f;
    __syncthreads();

    float accB[64];
    #pragma unroll
    for (int i = 0; i < 64; i++) accB[i] = 0.f;
    float ds[8] = {0,0,0,0,0,0,0,0};

    const float* xp0 = xln + ((size_t)b*Nq + (size_t)blockIdx.x*(TILE_TOK*ATPB2) + w*TPW)*Dq;

    for (int tile = 0; tile < ATPB2; tile++) {
        const float* xp = xp0 + (size_t)tile*TILE_TOK*Dq;
        float4 xa[TPW], xb[TPW];
        #pragma unroll
        for (int j = 0; j < TPW; j++) {
            xa[j] = *(const float4*)(xp + j*Dq + 4*l);
            xb[j] = *(const float4*)(xp + j*Dq + 128 + 4*l);
        }
        // phase A: partial logits over this lane's d-slice
        float pr[32];
        #pragma unroll
        for (int s = 0; s < 8; s++) {
            float4 qa = qk4[s*64 + l];
            float4 qb = qk4[s*64 + 32 + l];
            #pragma unroll
            for (int j = 0; j < TPW; j++) {
                float p = xa[j].x * qa.x;
                p = fmaf(xa[j].y, qa.y, p);
                p = fmaf(xa[j].z, qa.z, p);
                p = fmaf(xa[j].w, qa.w, p);
                p = fmaf(xb[j].x, qb.x, p);
                p = fmaf(xb[j].y, qb.y, p);
                p = fmaf(xb[j].z, qb.z, p);
                p = fmaf(xb[j].w, qb.w, p);
                pr[j*8 + s] = p;
            }
        }
        // full butterfly: every lane ends with all 32 complete logits
        #pragma unroll
        for (int off = 16; off > 0; off >>= 1) {
            #pragma unroll
            for (int i = 0; i < 32; i++)
                pr[i] += __shfl_xor_sync(0xffffffffu, pr[i], off);
        }
        // softmax over slots per token (replicated across lanes), + EPS
        #pragma unroll
        for (int j = 0; j < TPW; j++) {
            float lv[8], m = -1e30f;
            #pragma unroll
            for (int s = 0; s < 8; s++) { lv[s] = pr[j*8 + s] + cr[s]; m = fmaxf(m, lv[s]); }
            float sum = 0.f;
            #pragma unroll
            for (int s = 0; s < 8; s++) { lv[s] = __expf(lv[s] - m); sum += lv[s]; }
            float inv = __fdividef(1.f, sum);
            #pragma unroll
            for (int s = 0; s < 8; s++) {
                float a = fmaf(lv[s], inv, EPS_A);
                pr[j*8 + s] = a;
                ds[s] += a;
            }
        }
        // phase B: rank-accumulate numer partials in registers
        #pragma unroll
        for (int j = 0; j < TPW; j++) {
            #pragma unroll
            for (int s = 0; s < 8; s++) {
                float a = pr[j*8 + s];
                accB[s*8 + 0] = fmaf(a, xa[j].x, accB[s*8 + 0]);
                accB[s*8 + 1] = fmaf(a, xa[j].y, accB[s*8 + 1]);
                accB[s*8 + 2] = fmaf(a, xa[j].z, accB[s*8 + 2]);
                accB[s*8 + 3] = fmaf(a, xa[j].w, accB[s*8 + 3]);
                accB[s*8 + 4] = fmaf(a, xb[j].x, accB[s*8 + 4]);
                accB[s*8 + 5] = fmaf(a, xb[j].y, accB[s*8 + 5]);
                accB[s*8 + 6] = fmaf(a, xb[j].z, accB[s*8 + 6]);
                accB[s*8 + 7] = fmaf(a, xb[j].w, accB[s*8 + 7]);
            }
        }
    }
    // denom partials (values replicated per lane; lane 0 writes)
    if (l == 0) {
        #pragma unroll
        for (int s = 0; s < 8; s++) sds[w*8 + s] = ds[s];
    }
    // cross-warp reduce accB into red (serialized rounds, deterministic)
    for (int r = 0; r < 8; r++) {
        __syncthreads();
        if (w == r) {
            #pragma unroll
            for (int s = 0; s < 8; s++) {
                red[s*256 + 4*l + 0]       += accB[s*8 + 0];
                red[s*256 + 4*l + 1]       += accB[s*8 + 1];
                red[s*256 + 4*l + 2]       += accB[s*8 + 2];
                red[s*256 + 4*l + 3]       += accB[s*8 + 3];
                red[s*256 + 128 + 4*l + 0] += accB[s*8 + 4];
                red[s*256 + 128 + 4*l + 1] += accB[s*8 + 5];
                red[s*256 + 128 + 4*l + 2] += accB[s*8 + 6];
                red[s*256 + 128 + 4*l + 3] += accB[s*8 + 7];
            }
        }
    }
    __syncthreads();
    size_t pbase = ((size_t)blockIdx.x*ROWS + b*8)*Dq;
    #pragma unroll
    for (int i = 0; i < 8; i++) part[pbase + i*256 + t] = red[i*256 + t];
    if (t < 8) {
        float sum = 0.f;
        #pragma unroll
        for (int ww = 0; ww < 8; ww++) sum += sds[ww*8 + t];
        dpart[blockIdx.x*ROWS + b*8 + t] = sum;
    }
}

// -------------------- reduce partials over chunks and normalize --------------------
__global__ void reduce_norm_kernel(const float* __restrict__ part,
                                   const float* __restrict__ dpart,
                                   float* __restrict__ numer) {
    int row = blockIdx.x, t = threadIdx.x;
    float s = 0.f, dn = 0.f;
    #pragma unroll
    for (int c = 0; c < ACH; c++) {
        s  += part[((size_t)c*ROWS + row)*Dq + t];
        dn += dpart[c*ROWS + row];
    }
    numer[(size_t)row*Dq + t] = s / dn;
}

// -------------------- GRU cell elementwise --------------------
__global__ void gru_kernel(const float* __restrict__ gx, const float* __restrict__ gh,
                           const float* __restrict__ slots, float* __restrict__ h) {
    int row = blockIdx.x, d = threadIdx.x;
    const float* gxr = gx + (size_t)row*768;
    const float* ghr = gh + (size_t)row*768;
    float r = 1.f/(1.f + expf(-(gxr[d]       + ghr[d])));
    float z = 1.f/(1.f + expf(-(gxr[256 + d] + ghr[256 + d])));
    float n = tanhf(gxr[512 + d] + r*ghr[512 + d]);
    h[(size_t)row*Dq + d] = (1.f - z)*n + z*slots[(size_t)row*Dq + d];
}

// -------------------- host --------------------
extern "C" void kernel_launch(void* const* d_in, const int* in_sizes, int n_in,
                              void* d_out, int out_size) {
    (void)in_sizes; (void)n_in; (void)out_size;
    const float* inputs    = (const float*)d_in[0];
    const float* query_pos = (const float*)d_in[1];
    const float* wq   = (const float*)d_in[2];
    const float* bq   = (const float*)d_in[3];
    const float* wk   = (const float*)d_in[4];
    const float* bk   = (const float*)d_in[5];
    const float* wv   = (const float*)d_in[6];
    const float* bv   = (const float*)d_in[7];
    const float* w_ih = (const float*)d_in[8];
    const float* b_ih = (const float*)d_in[9];
    const float* w_hh = (const float*)d_in[10];
    const float* b_hh = (const float*)d_in[11];
    const float* w1   = (const float*)d_in[12];
    const float* b1   = (const float*)d_in[13];
    const float* w2   = (const float*)d_in[14];
    const float* b2   = (const float*)d_in[15];
    const float* ln_in_w = (const float*)d_in[16];
    const float* ln_in_b = (const float*)d_in[17];
    const float* ln_s_w  = (const float*)d_in[18];
    const float* ln_s_b  = (const float*)d_in[19];
    const float* ln_ff_w = (const float*)d_in[20];
    const float* ln_ff_b = (const float*)d_in[21];
    float* out = (float*)d_out;

    float *xln, *slots, *s, *qkb, *c, *numer, *part, *dpart, *upd, *gx, *gh, *h, *hln, *ff1;
    float *w2t, *vb, *bqk, *cconst;
    cudaGetSymbolAddress((void**)&xln,   g_xln);
    cudaGetSymbolAddress((void**)&slots, g_slots);
    cudaGetSymbolAddress((void**)&s,     g_s);
    cudaGetSymbolAddress((void**)&qkb,   g_qk);
    cudaGetSymbolAddress((void**)&c,     g_c);
    cudaGetSymbolAddress((void**)&numer, g_numer);
    cudaGetSymbolAddress((void**)&part,  g_part);
    cudaGetSymbolAddress((void**)&dpart, g_dpart);
    cudaGetSymbolAddress((void**)&upd,   g_upd);
    cudaGetSymbolAddress((void**)&gx,    g_gx);
    cudaGetSymbolAddress((void**)&gh,    g_gh);
    cudaGetSymbolAddress((void**)&h,     g_h);
    cudaGetSymbolAddress((void**)&hln,   g_hln);
    cudaGetSymbolAddress((void**)&ff1,   g_ff1);
    cudaGetSymbolAddress((void**)&w2t,   g_w2t);
    cudaGetSymbolAddress((void**)&vb,    g_vb);
    cudaGetSymbolAddress((void**)&bqk,   g_bqk);
    cudaGetSymbolAddress((void**)&cconst,g_cconst);

    // once per launch
    ln_rows_kernel<<<Bq*Nq, 256>>>(inputs, ln_in_w, ln_in_b, xln);
    init_slots_kernel<<<ROWS, 256>>>(query_pos, slots);
    prep_w2_kernel<<<dim3(4, 4), 256>>>(wq, wk, w2t);
    prep_small_kernel<<<1, 256>>>(wq, wk, bq, bk, vb, bqk, cconst);

    for (int it = 0; it < 4; it++) {
        float* slots_out = (it == 3) ? out : slots;
        ln_rows_kernel<<<ROWS, 256>>>(slots, ln_s_w, ln_s_b, s);
        // qk = s @ W2T^T + bqk  (W2 folded: no q materialization)
        gemm64_kernel<false><<<dim3(4, 8), 256>>>(s, w2t, bqk, nullptr, qkb, ROWS, Dq, Dq);
        cvec2_kernel<<<ROWS, 256>>>(s, vb, cconst, c);
        // streaming attention
        attend2_kernel<<<dim3(ACH, Bq), 256>>>(xln, qkb, c, part, dpart);
        reduce_norm_kernel<<<ROWS, 256>>>(part, dpart, numer);
        // updates = (numer/denom) @ wv.T + bv
        gemm64_kernel<false><<<dim3(4, 8), 256>>>(numer, wv, bv, nullptr, upd, ROWS, Dq, Dq);
        // GRU gates (xn/hn must stay separate for n = tanh(xn + r*hn))
        gemm64_kernel<false><<<dim3(12, 8), 256>>>(upd,   w_ih, b_ih, nullptr, gx, ROWS, 3*Dq, Dq);
        gemm64_kernel<false><<<dim3(12, 8), 256>>>(slots, w_hh, b_hh, nullptr, gh, ROWS, 3*Dq, Dq);
        gru_kernel<<<ROWS, 256>>>(gx, gh, slots, h);
        // FF
        ln_rows_kernel<<<ROWS, 256>>>(h, ln_ff_w, ln_ff_b, hln);
        gemm64_kernel<true ><<<dim3(8, 8), 256>>>(hln, w1, b1, nullptr, ff1, ROWS, Hq, Dq);
        gemm64_kernel<false><<<dim3(4, 8), 256>>>(ff1, w2, b2, h, slots_out, ROWS, Dq, Hq);
    }
}

// round 8
// speedup vs baseline: 1.4558x; 1.1671x over previous
#include <cuda_runtime.h>
#include <cuda_bf16.h>
#include <math.h>

#define Bq 64
#define Nq 4096
#define Dq 256
#define Hq 512
#define ROWS 512              // Bq*8 slot rows
#define SCALEF 0.0625f        // 256^-0.5
#define LN_EPS 1e-5f
#define EPS_A 1e-8f

#define TPW 4                 // tokens per warp (attend)
#define TILE_TOK 32           // tokens per block-tile (8 warps * 4)
#define ATPB2 8               // tiles per block -> 256 tokens/block
#define ACH (Nq/(TILE_TOK*ATPB2))   // 16 chunks per batch

// -------------------- scratch (device globals; no allocation) --------------------
__device__ float g_xln[(size_t)Bq*Nq*Dq];      // 256 MB: LN(inputs)
__device__ float g_slots[ROWS*Dq];
__device__ float g_s[ROWS*Dq];
__device__ float g_qk[ROWS*Dq];
__device__ float g_c[ROWS];
__device__ float g_numer[ROWS*Dq];
__device__ float g_part[(size_t)ACH*ROWS*Dq];
__device__ float g_dpart[ACH*ROWS];
__device__ float g_upd[ROWS*Dq];
__device__ float g_gx[ROWS*3*Dq];
__device__ float g_gh[ROWS*3*Dq];
__device__ float g_h[ROWS*Dq];
__device__ float g_hln[ROWS*Dq];
__device__ float g_ff1[ROWS*Hq];
__device__ float g_w2t[Dq*Dq];     // w2t[n][k] = SCALE * sum_e wq[e][k]*wk[e][n]
__device__ float g_vb[Dq];         // vb[k] = SCALE * sum_e wq[e][k]*bk[e]
__device__ float g_bqk[Dq];        // bqk[n] = SCALE * sum_e bq[e]*wk[e][n]
__device__ float g_cconst[1];      // SCALE * (bq . bk)

// -------------------- LayerNorm over rows of width 256 (plain) --------------------
__global__ void ln_rows_kernel(const float* __restrict__ x, const float* __restrict__ w,
                               const float* __restrict__ bb, float* __restrict__ y) {
    __shared__ float sm[8];
    __shared__ float sm2[8];
    size_t row = blockIdx.x;
    int t = threadIdx.x;
    float v = x[row*Dq + t];
    float s = v;
    #pragma unroll
    for (int o = 16; o > 0; o >>= 1) s += __shfl_xor_sync(0xffffffffu, s, o);
    if ((t & 31) == 0) sm[t >> 5] = s;
    __syncthreads();
    float mean = 0.f;
    #pragma unroll
    for (int i = 0; i < 8; i++) mean += sm[i];
    mean *= (1.0f/Dq);
    float d = v - mean;
    float sq = d*d;
    #pragma unroll
    for (int o = 16; o > 0; o >>= 1) sq += __shfl_xor_sync(0xffffffffu, sq, o);
    if ((t & 31) == 0) sm2[t >> 5] = sq;
    __syncthreads();
    float var = 0.f;
    #pragma unroll
    for (int i = 0; i < 8; i++) var += sm2[i];
    var *= (1.0f/Dq);
    y[row*Dq + t] = d * rsqrtf(var + LN_EPS) * w[t] + bb[t];
}

// -------------------- LN(slots) fused with c = s.vb + cconst --------------------
__global__ void lncv_kernel(const float* __restrict__ x, const float* __restrict__ w,
                            const float* __restrict__ bb, const float* __restrict__ vb,
                            const float* __restrict__ cconst,
                            float* __restrict__ y, float* __restrict__ c) {
    __shared__ float sm[8];
    __shared__ float sm2[8];
    __shared__ float sm3[8];
    size_t row = blockIdx.x;
    int t = threadIdx.x;
    float v = x[row*Dq + t];
    float s = v;
    #pragma unroll
    for (int o = 16; o > 0; o >>= 1) s += __shfl_xor_sync(0xffffffffu, s, o);
    if ((t & 31) == 0) sm[t >> 5] = s;
    __syncthreads();
    float mean = 0.f;
    #pragma unroll
    for (int i = 0; i < 8; i++) mean += sm[i];
    mean *= (1.0f/Dq);
    float d = v - mean;
    float sq = d*d;
    #pragma unroll
    for (int o = 16; o > 0; o >>= 1) sq += __shfl_xor_sync(0xffffffffu, sq, o);
    if ((t & 31) == 0) sm2[t >> 5] = sq;
    __syncthreads();
    float var = 0.f;
    #pragma unroll
    for (int i = 0; i < 8; i++) var += sm2[i];
    var *= (1.0f/Dq);
    float out = d * rsqrtf(var + LN_EPS) * w[t] + bb[t];
    y[row*Dq + t] = out;
    float p = out * vb[t];
    #pragma unroll
    for (int o = 16; o > 0; o >>= 1) p += __shfl_xor_sync(0xffffffffu, p, o);
    if ((t & 31) == 0) sm3[t >> 5] = p;
    __syncthreads();
    if (t == 0) {
        float sum = 0.f;
        #pragma unroll
        for (int i = 0; i < 8; i++) sum += sm3[i];
        c[row] = sum + cconst[0];
    }
}

// -------------------- init slots from query_pos --------------------
__global__ void init_slots_kernel(const float* __restrict__ qp, float* __restrict__ slots) {
    int row = blockIdx.x, d = threadIdx.x;
    slots[row*Dq + d] = qp[(row & 7)*Dq + d];
}

// -------------------- precompute W2T = SCALE * (wq.T @ wk) stored [n][k] ----------
__global__ void __launch_bounds__(256) prep_w2_kernel(const float* __restrict__ wq,
                                                      const float* __restrict__ wk,
                                                      float* __restrict__ w2t) {
    __shared__ float As[64][68];  // wq tile: [e][m(k-col)]
    __shared__ float Bs[64][68];  // wk tile: [e][n]
    int n0 = blockIdx.y * 64, m0 = blockIdx.x * 64;
    int t = threadIdx.x, tx = t & 15, ty = t >> 4;
    float acc[4][4] = {};
    for (int e0 = 0; e0 < Dq; e0 += 64) {
        #pragma unroll
        for (int i = 0; i < 4; i++) {
            int f4 = t + i*256;
            int r = f4 >> 4, cq = f4 & 15;
            float4 va = *(const float4*)(wq + (size_t)(e0 + r)*Dq + m0 + 4*cq);
            *(float4*)&As[r][4*cq] = va;
            float4 vb4 = *(const float4*)(wk + (size_t)(e0 + r)*Dq + n0 + 4*cq);
            *(float4*)&Bs[r][4*cq] = vb4;
        }
        __syncthreads();
        #pragma unroll
        for (int kk = 0; kk < 64; kk++) {
            float nv[4], mv[4];
            #pragma unroll
            for (int i = 0; i < 4; i++) nv[i] = Bs[kk][4*ty + i];
            #pragma unroll
            for (int j = 0; j < 4; j++) mv[j] = As[kk][4*tx + j];
            #pragma unroll
            for (int i = 0; i < 4; i++)
                #pragma unroll
                for (int j = 0; j < 4; j++)
                    acc[i][j] = fmaf(nv[i], mv[j], acc[i][j]);
        }
        __syncthreads();
    }
    #pragma unroll
    for (int i = 0; i < 4; i++)
        #pragma unroll
        for (int j = 0; j < 4; j++)
            w2t[(size_t)(n0 + 4*ty + i)*Dq + m0 + 4*tx + j] = SCALEF * acc[i][j];
}

// -------------------- precompute vb, bqk, cconst (parallel) --------------------
// grid = 16 blocks: 0..7 -> vb chunks of 32; 8..15 -> bqk chunks; block 0 also cconst.
__global__ void prep_small2_kernel(const float* __restrict__ wq, const float* __restrict__ wk,
                                   const float* __restrict__ bq, const float* __restrict__ bk,
                                   float* __restrict__ vb, float* __restrict__ bqk,
                                   float* __restrict__ cconst) {
    __shared__ float red[8][33];
    int blk = blockIdx.x;
    int t = threadIdx.x;
    int to = t & 31, eg = t >> 5;
    bool isB = blk >= 8;
    int t0 = (blk & 7)*32 + to;
    float p = 0.f;
    #pragma unroll 4
    for (int e = eg*32; e < eg*32 + 32; e++) {
        p = isB ? fmaf(bq[e], wk[(size_t)e*Dq + t0], p)
                : fmaf(wq[(size_t)e*Dq + t0], bk[e], p);
    }
    red[eg][to] = p;
    __syncthreads();
    if (t < 32) {
        float s = 0.f;
        #pragma unroll
        for (int i = 0; i < 8; i++) s += red[i][t];
        (isB ? bqk : vb)[(blk & 7)*32 + t] = SCALEF * s;
    }
    if (blk == 0) {
        __syncthreads();
        float q = bq[t]*bk[t];
        #pragma unroll
        for (int o = 16; o > 0; o >>= 1) q += __shfl_xor_sync(0xffffffffu, q, o);
        if ((t & 31) == 0) red[0][t >> 5] = q;
        __syncthreads();
        if (t == 0) {
            float s = 0.f;
            #pragma unroll
            for (int i = 0; i < 8; i++) s += red[0][i];
            cconst[0] = SCALEF * s;
        }
    }
}

// -------------------- GEMM 64x64 tile, BK=64: C = A@W^T + bias (+res) (relu) ------
template<bool RELU>
__device__ __forceinline__ void gemm64_body(const float* __restrict__ A,
                                            const float* __restrict__ W,
                                            const float* __restrict__ bias,
                                            const float* __restrict__ res,
                                            float* __restrict__ C,
                                            int N, int K, int m0, int n0) {
    __shared__ float As[64][65];   // [m][k]
    __shared__ float Bs[64][65];   // [n][k]
    int t = threadIdx.x, tx = t & 15, ty = t >> 4;
    float acc[4][4] = {};
    for (int k0 = 0; k0 < K; k0 += 64) {
        #pragma unroll
        for (int i = 0; i < 4; i++) {
            int f4 = t + i*256;
            int r = f4 >> 4, kq = f4 & 15;
            float4 va = *(const float4*)(A + (size_t)(m0 + r)*K + k0 + 4*kq);
            As[r][4*kq + 0] = va.x; As[r][4*kq + 1] = va.y;
            As[r][4*kq + 2] = va.z; As[r][4*kq + 3] = va.w;
            float4 vb4 = *(const float4*)(W + (size_t)(n0 + r)*K + k0 + 4*kq);
            Bs[r][4*kq + 0] = vb4.x; Bs[r][4*kq + 1] = vb4.y;
            Bs[r][4*kq + 2] = vb4.z; Bs[r][4*kq + 3] = vb4.w;
        }
        __syncthreads();
        #pragma unroll
        for (int kk = 0; kk < 64; kk++) {
            float a[4], b[4];
            #pragma unroll
            for (int i = 0; i < 4; i++) a[i] = As[4*ty + i][kk];
            #pragma unroll
            for (int j = 0; j < 4; j++) b[j] = Bs[4*tx + j][kk];
            #pragma unroll
            for (int i = 0; i < 4; i++)
                #pragma unroll
                for (int j = 0; j < 4; j++)
                    acc[i][j] = fmaf(a[i], b[j], acc[i][j]);
        }
        __syncthreads();
    }
    #pragma unroll
    for (int i = 0; i < 4; i++) {
        int m = m0 + 4*ty + i;
        #pragma unroll
        for (int j = 0; j < 4; j++) {
            int n = n0 + 4*tx + j;
            float v = acc[i][j];
            if (bias) v += bias[n];
            if (RELU) v = fmaxf(v, 0.f);
            if (res)  v += res[(size_t)m*N + n];
            C[(size_t)m*N + n] = v;
        }
    }
}

template<bool RELU>
__global__ void __launch_bounds__(256) gemm64_kernel(const float* __restrict__ A,
                                                     const float* __restrict__ W,
                                                     const float* __restrict__ bias,
                                                     const float* __restrict__ res,
                                                     float* __restrict__ C,
                                                     int N, int K) {
    gemm64_body<RELU>(A, W, bias, res, C, N, K, blockIdx.y*64, blockIdx.x*64);
}

// dual GEMM (gx & gh) selected by blockIdx.z
__global__ void __launch_bounds__(256) gemm64_dual_kernel(const float* __restrict__ A0,
                                                          const float* __restrict__ W0,
                                                          const float* __restrict__ b0,
                                                          float* __restrict__ C0,
                                                          const float* __restrict__ A1,
                                                          const float* __restrict__ W1,
                                                          const float* __restrict__ b1,
                                                          float* __restrict__ C1,
                                                          int N, int K) {
    if (blockIdx.z == 0)
        gemm64_body<false>(A0, W0, b0, nullptr, C0, N, K, blockIdx.y*64, blockIdx.x*64);
    else
        gemm64_body<false>(A1, W1, b1, nullptr, C1, N, K, blockIdx.y*64, blockIdx.x*64);
}

// -------------------- attend v3: swap-reduce logits, x in registers ---------------
__global__ void __launch_bounds__(256, 1) attend3_kernel(const float* __restrict__ xln,
                                                         const float* __restrict__ qk,
                                                         const float* __restrict__ cc,
                                                         float* __restrict__ part,
                                                         float* __restrict__ dpart) {
    __shared__ float4 qk4[512];   // [s][64] float4 view of qk[b]
    __shared__ float red[2048];   // [s][256] block partial numer
    __shared__ float sds[64];     // [warp][slot] partial denom
    __shared__ float a_sh[8][32]; // per-warp attention weights for 32 (tok,slot) pairs
    int b = blockIdx.y;
    int t = threadIdx.x, w = t >> 5, l = t & 31;
    {
        const float4* src = (const float4*)(qk + (size_t)b*8*Dq);
        qk4[t]       = src[t];
        qk4[t + 256] = src[t + 256];
    }
    float cr = cc[b*8 + (l & 7)];
    #pragma unroll
    for (int i = 0; i < 8; i++) red[t + i*256] = 0.f;
    __syncthreads();

    float accB[64];
    #pragma unroll
    for (int i = 0; i < 64; i++) accB[i] = 0.f;
    float dsl = 0.f;

    const float* xp0 = xln + ((size_t)b*Nq + (size_t)blockIdx.x*(TILE_TOK*ATPB2) + w*TPW)*Dq;

    for (int tile = 0; tile < ATPB2; tile++) {
        const float* xp = xp0 + (size_t)tile*TILE_TOK*Dq;
        float4 xa[TPW], xb[TPW];
        #pragma unroll
        for (int j = 0; j < TPW; j++) {
            xa[j] = *(const float4*)(xp + j*Dq + 4*l);
            xb[j] = *(const float4*)(xp + j*Dq + 128 + 4*l);
        }
        // phase A: per-lane partial logits for all 32 (token j, slot s) entries
        float v[32];
        #pragma unroll
        for (int s = 0; s < 8; s++) {
            float4 qa = qk4[s*64 + l];
            float4 qb = qk4[s*64 + 32 + l];
            #pragma unroll
            for (int j = 0; j < TPW; j++) {
                float p = xa[j].x * qa.x;
                p = fmaf(xa[j].y, qa.y, p);
                p = fmaf(xa[j].z, qa.z, p);
                p = fmaf(xa[j].w, qa.w, p);
                p = fmaf(xb[j].x, qb.x, p);
                p = fmaf(xb[j].y, qb.y, p);
                p = fmaf(xb[j].z, qb.z, p);
                p = fmaf(xb[j].w, qb.w, p);
                v[j*8 + s] = p;
            }
        }
        // swap-reduce: 31 shfl; lane l ends with complete logit for entry l
        #pragma unroll
        for (int half = 16; half >= 1; half >>= 1) {
            int hi = l & half;
            #pragma unroll
            for (int i = 0; i < half; i++) {
                float send = hi ? v[i] : v[i + half];
                float keep = hi ? v[i + half] : v[i];
                v[i] = keep + __shfl_xor_sync(0xffffffffu, send, half);
            }
        }
        // softmax over the 8-lane slot group (l>>3 = token)
        float lg = v[0] + cr;
        float m = lg;
        #pragma unroll
        for (int o = 1; o <= 4; o <<= 1) m = fmaxf(m, __shfl_xor_sync(0xffffffffu, m, o));
        float e = __expf(lg - m);
        float sum = e;
        #pragma unroll
        for (int o = 1; o <= 4; o <<= 1) sum += __shfl_xor_sync(0xffffffffu, sum, o);
        float a = fmaf(e, __fdividef(1.f, sum), EPS_A);
        dsl += a;
        __syncwarp();
        a_sh[w][l] = a;
        __syncwarp();
        // phase B: rank-accumulate numer partials (a broadcast from smem)
        #pragma unroll
        for (int j = 0; j < TPW; j++) {
            float4 a0 = *(const float4*)&a_sh[w][j*8];
            float4 a1 = *(const float4*)&a_sh[w][j*8 + 4];
            accB[0*8 + 0] = fmaf(a0.x, xa[j].x, accB[0*8 + 0]);
            accB[0*8 + 1] = fmaf(a0.x, xa[j].y, accB[0*8 + 1]);
            accB[0*8 + 2] = fmaf(a0.x, xa[j].z, accB[0*8 + 2]);
            accB[0*8 + 3] = fmaf(a0.x, xa[j].w, accB[0*8 + 3]);
            accB[0*8 + 4] = fmaf(a0.x, xb[j].x, accB[0*8 + 4]);
            accB[0*8 + 5] = fmaf(a0.x, xb[j].y, accB[0*8 + 5]);
            accB[0*8 + 6] = fmaf(a0.x, xb[j].z, accB[0*8 + 6]);
            accB[0*8 + 7] = fmaf(a0.x, xb[j].w, accB[0*8 + 7]);
            accB[1*8 + 0] = fmaf(a0.y, xa[j].x, accB[1*8 + 0]);
            accB[1*8 + 1] = fmaf(a0.y, xa[j].y, accB[1*8 + 1]);
            accB[1*8 + 2] = fmaf(a0.y, xa[j].z, accB[1*8 + 2]);
            accB[1*8 + 3] = fmaf(a0.y, xa[j].w, accB[1*8 + 3]);
            accB[1*8 + 4] = fmaf(a0.y, xb[j].x, accB[1*8 + 4]);
            accB[1*8 + 5] = fmaf(a0.y, xb[j].y, accB[1*8 + 5]);
            accB[1*8 + 6] = fmaf(a0.y, xb[j].z, accB[1*8 + 6]);
            accB[1*8 + 7] = fmaf(a0.y, xb[j].w, accB[1*8 + 7]);
            accB[2*8 + 0] = fmaf(a0.z, xa[j].x, accB[2*8 + 0]);
            accB[2*8 + 1] = fmaf(a0.z, xa[j].y, accB[2*8 + 1]);
            accB[2*8 + 2] = fmaf(a0.z, xa[j].z, accB[2*8 + 2]);
            accB[2*8 + 3] = fmaf(a0.z, xa[j].w, accB[2*8 + 3]);
            accB[2*8 + 4] = fmaf(a0.z, xb[j].x, accB[2*8 + 4]);
            accB[2*8 + 5] = fmaf(a0.z, xb[j].y, accB[2*8 + 5]);
            accB[2*8 + 6] = fmaf(a0.z, xb[j].z, accB[2*8 + 6]);
            accB[2*8 + 7] = fmaf(a0.z, xb[j].w, accB[2*8 + 7]);
            accB[3*8 + 0] = fmaf(a0.w, xa[j].x, accB[3*8 + 0]);
            accB[3*8 + 1] = fmaf(a0.w, xa[j].y, accB[3*8 + 1]);
            accB[3*8 + 2] = fmaf(a0.w, xa[j].z, accB[3*8 + 2]);
            accB[3*8 + 3] = fmaf(a0.w, xa[j].w, accB[3*8 + 3]);
            accB[3*8 + 4] = fmaf(a0.w, xb[j].x, accB[3*8 + 4]);
            accB[3*8 + 5] = fmaf(a0.w, xb[j].y, accB[3*8 + 5]);
            accB[3*8 + 6] = fmaf(a0.w, xb[j].z, accB[3*8 + 6]);
            accB[3*8 + 7] = fmaf(a0.w, xb[j].w, accB[3*8 + 7]);
            accB[4*8 + 0] = fmaf(a1.x, xa[j].x, accB[4*8 + 0]);
            accB[4*8 + 1] = fmaf(a1.x, xa[j].y, accB[4*8 + 1]);
            accB[4*8 + 2] = fmaf(a1.x, xa[j].z, accB[4*8 + 2]);
            accB[4*8 + 3] = fmaf(a1.x, xa[j].w, accB[4*8 + 3]);
            accB[4*8 + 4] = fmaf(a1.x, xb[j].x, accB[4*8 + 4]);
            accB[4*8 + 5] = fmaf(a1.x, xb[j].y, accB[4*8 + 5]);
            accB[4*8 + 6] = fmaf(a1.x, xb[j].z, accB[4*8 + 6]);
            accB[4*8 + 7] = fmaf(a1.x, xb[j].w, accB[4*8 + 7]);
            accB[5*8 + 0] = fmaf(a1.y, xa[j].x, accB[5*8 + 0]);
            accB[5*8 + 1] = fmaf(a1.y, xa[j].y, accB[5*8 + 1]);
            accB[5*8 + 2] = fmaf(a1.y, xa[j].z, accB[5*8 + 2]);
            accB[5*8 + 3] = fmaf(a1.y, xa[j].w, accB[5*8 + 3]);
            accB[5*8 + 4] = fmaf(a1.y, xb[j].x, accB[5*8 + 4]);
            accB[5*8 + 5] = fmaf(a1.y, xb[j].y, accB[5*8 + 5]);
            accB[5*8 + 6] = fmaf(a1.y, xb[j].z, accB[5*8 + 6]);
            accB[5*8 + 7] = fmaf(a1.y, xb[j].w, accB[5*8 + 7]);
            accB[6*8 + 0] = fmaf(a1.z, xa[j].x, accB[6*8 + 0]);
            accB[6*8 + 1] = fmaf(a1.z, xa[j].y, accB[6*8 + 1]);
            accB[6*8 + 2] = fmaf(a1.z, xa[j].z, accB[6*8 + 2]);
            accB[6*8 + 3] = fmaf(a1.z, xa[j].w, accB[6*8 + 3]);
            accB[6*8 + 4] = fmaf(a1.z, xb[j].x, accB[6*8 + 4]);
            accB[6*8 + 5] = fmaf(a1.z, xb[j].y, accB[6*8 + 5]);
            accB[6*8 + 6] = fmaf(a1.z, xb[j].z, accB[6*8 + 6]);
            accB[6*8 + 7] = fmaf(a1.z, xb[j].w, accB[6*8 + 7]);
            accB[7*8 + 0] = fmaf(a1.w, xa[j].x, accB[7*8 + 0]);
            accB[7*8 + 1] = fmaf(a1.w, xa[j].y, accB[7*8 + 1]);
            accB[7*8 + 2] = fmaf(a1.w, xa[j].z, accB[7*8 + 2]);
            accB[7*8 + 3] = fmaf(a1.w, xa[j].w, accB[7*8 + 3]);
            accB[7*8 + 4] = fmaf(a1.w, xb[j].x, accB[7*8 + 4]);
            accB[7*8 + 5] = fmaf(a1.w, xb[j].y, accB[7*8 + 5]);
            accB[7*8 + 6] = fmaf(a1.w, xb[j].z, accB[7*8 + 6]);
            accB[7*8 + 7] = fmaf(a1.w, xb[j].w, accB[7*8 + 7]);
        }
    }
    // denom: lane holds sum over its own (tok-group, slot); reduce over tok-groups
    dsl += __shfl_xor_sync(0xffffffffu, dsl, 8);
    dsl += __shfl_xor_sync(0xffffffffu, dsl, 16);
    if (l < 8) sds[w*8 + l] = dsl;
    // cross-warp reduce accB into red (serialized rounds, deterministic)
    for (int r = 0; r < 8; r++) {
        __syncthreads();
        if (w == r) {
            #pragma unroll
            for (int s = 0; s < 8; s++) {
                red[s*256 + 4*l + 0]       += accB[s*8 + 0];
                red[s*256 + 4*l + 1]       += accB[s*8 + 1];
                red[s*256 + 4*l + 2]       += accB[s*8 + 2];
                red[s*256 + 4*l + 3]       += accB[s*8 + 3];
                red[s*256 + 128 + 4*l + 0] += accB[s*8 + 4];
                red[s*256 + 128 + 4*l + 1] += accB[s*8 + 5];
                red[s*256 + 128 + 4*l + 2] += accB[s*8 + 6];
                red[s*256 + 128 + 4*l + 3] += accB[s*8 + 7];
            }
        }
    }
    __syncthreads();
    size_t pbase = ((size_t)blockIdx.x*ROWS + b*8)*Dq;
    #pragma unroll
    for (int i = 0; i < 8; i++) part[pbase + i*256 + t] = red[i*256 + t];
    if (t < 8) {
        float sum = 0.f;
        #pragma unroll
        for (int ww = 0; ww < 8; ww++) sum += sds[ww*8 + t];
        dpart[blockIdx.x*ROWS + b*8 + t] = sum;
    }
}

// -------------------- reduce partials over chunks and normalize --------------------
__global__ void reduce_norm_kernel(const float* __restrict__ part,
                                   const float* __restrict__ dpart,
                                   float* __restrict__ numer) {
    int row = blockIdx.x, t = threadIdx.x;
    float s = 0.f, dn = 0.f;
    #pragma unroll
    for (int c = 0; c < ACH; c++) {
        s  += part[((size_t)c*ROWS + row)*Dq + t];
        dn += dpart[c*ROWS + row];
    }
    numer[(size_t)row*Dq + t] = s / dn;
}

// -------------------- GRU cell fused with LN_ff --------------------
__global__ void gruln_kernel(const float* __restrict__ gx, const float* __restrict__ gh,
                             const float* __restrict__ slots,
                             const float* __restrict__ lw, const float* __restrict__ lb,
                             float* __restrict__ h, float* __restrict__ hln) {
    __shared__ float sm[8];
    __shared__ float sm2[8];
    int row = blockIdx.x, t = threadIdx.x;
    const float* gxr = gx + (size_t)row*768;
    const float* ghr = gh + (size_t)row*768;
    float r = 1.f/(1.f + expf(-(gxr[t]       + ghr[t])));
    float z = 1.f/(1.f + expf(-(gxr[256 + t] + ghr[256 + t])));
    float n = tanhf(gxr[512 + t] + r*ghr[512 + t]);
    float hv = (1.f - z)*n + z*slots[(size_t)row*Dq + t];
    h[(size_t)row*Dq + t] = hv;
    // LN(hv)
    float s = hv;
    #pragma unroll
    for (int o = 16; o > 0; o >>= 1) s += __shfl_xor_sync(0xffffffffu, s, o);
    if ((t & 31) == 0) sm[t >> 5] = s;
    __syncthreads();
    float mean = 0.f;
    #pragma unroll
    for (int i = 0; i < 8; i++) mean += sm[i];
    mean *= (1.0f/Dq);
    float d = hv - mean;
    float sq = d*d;
    #pragma unroll
    for (int o = 16; o > 0; o >>= 1) sq += __shfl_xor_sync(0xffffffffu, sq, o);
    if ((t & 31) == 0) sm2[t >> 5] = sq;
    __syncthreads();
    float var = 0.f;
    #pragma unroll
    for (int i = 0; i < 8; i++) var += sm2[i];
    var *= (1.0f/Dq);
    hln[(size_t)row*Dq + t] = d * rsqrtf(var + LN_EPS) * lw[t] + lb[t];
}

// -------------------- host --------------------
extern "C" void kernel_launch(void* const* d_in, const int* in_sizes, int n_in,
                              void* d_out, int out_size) {
    (void)in_sizes; (void)n_in; (void)out_size;
    const float* inputs    = (const float*)d_in[0];
    const float* query_pos = (const float*)d_in[1];
    const float* wq   = (const float*)d_in[2];
    const float* bq   = (const float*)d_in[3];
    const float* wk   = (const float*)d_in[4];
    const float* bk   = (const float*)d_in[5];
    const float* wv   = (const float*)d_in[6];
    const float* bv   = (const float*)d_in[7];
    const float* w_ih = (const float*)d_in[8];
    const float* b_ih = (const float*)d_in[9];
    const float* w_hh = (const float*)d_in[10];
    const float* b_hh = (const float*)d_in[11];
    const float* w1   = (const float*)d_in[12];
    const float* b1   = (const float*)d_in[13];
    const float* w2   = (const float*)d_in[14];
    const float* b2   = (const float*)d_in[15];
    const float* ln_in_w = (const float*)d_in[16];
    const float* ln_in_b = (const float*)d_in[17];
    const float* ln_s_w  = (const float*)d_in[18];
    const float* ln_s_b  = (const float*)d_in[19];
    const float* ln_ff_w = (const float*)d_in[20];
    const float* ln_ff_b = (const float*)d_in[21];
    float* out = (float*)d_out;

    float *xln, *slots, *s, *qkb, *c, *numer, *part, *dpart, *upd, *gx, *gh, *h, *hln, *ff1;
    float *w2t, *vb, *bqk, *cconst;
    cudaGetSymbolAddress((void**)&xln,   g_xln);
    cudaGetSymbolAddress((void**)&slots, g_slots);
    cudaGetSymbolAddress((void**)&s,     g_s);
    cudaGetSymbolAddress((void**)&qkb,   g_qk);
    cudaGetSymbolAddress((void**)&c,     g_c);
    cudaGetSymbolAddress((void**)&numer, g_numer);
    cudaGetSymbolAddress((void**)&part,  g_part);
    cudaGetSymbolAddress((void**)&dpart, g_dpart);
    cudaGetSymbolAddress((void**)&upd,   g_upd);
    cudaGetSymbolAddress((void**)&gx,    g_gx);
    cudaGetSymbolAddress((void**)&gh,    g_gh);
    cudaGetSymbolAddress((void**)&h,     g_h);
    cudaGetSymbolAddress((void**)&hln,   g_hln);
    cudaGetSymbolAddress((void**)&ff1,   g_ff1);
    cudaGetSymbolAddress((void**)&w2t,   g_w2t);
    cudaGetSymbolAddress((void**)&vb,    g_vb);
    cudaGetSymbolAddress((void**)&bqk,   g_bqk);
    cudaGetSymbolAddress((void**)&cconst,g_cconst);

    // once per launch
    ln_rows_kernel<<<Bq*Nq, 256>>>(inputs, ln_in_w, ln_in_b, xln);
    init_slots_kernel<<<ROWS, 256>>>(query_pos, slots);
    prep_w2_kernel<<<dim3(4, 4), 256>>>(wq, wk, w2t);
    prep_small2_kernel<<<16, 256>>>(wq, wk, bq, bk, vb, bqk, cconst);

    for (int it = 0; it < 4; it++) {
        float* slots_out = (it == 3) ? out : slots;
        lncv_kernel<<<ROWS, 256>>>(slots, ln_s_w, ln_s_b, vb, cconst, s, c);
        gemm64_kernel<false><<<dim3(4, 8), 256>>>(s, w2t, bqk, nullptr, qkb, Dq, Dq);
        attend3_kernel<<<dim3(ACH, Bq), 256>>>(xln, qkb, c, part, dpart);
        reduce_norm_kernel<<<ROWS, 256>>>(part, dpart, numer);
        gemm64_kernel<false><<<dim3(4, 8), 256>>>(numer, wv, bv, nullptr, upd, Dq, Dq);
        gemm64_dual_kernel<<<dim3(12, 8, 2), 256>>>(upd, w_ih, b_ih, gx,
                                                    slots, w_hh, b_hh, gh, 3*Dq, Dq);
        gruln_kernel<<<ROWS, 256>>>(gx, gh, slots, ln_ff_w, ln_ff_b, h, hln);
        gemm64_kernel<true ><<<dim3(8, 8), 256>>>(hln, w1, b1, nullptr, ff1, Hq, Dq);
        gemm64_kernel<false><<<dim3(4, 8), 256>>>(ff1, w2, b2, h, slots_out, Dq, Hq);
    }
}